// round 1
// baseline (speedup 1.0000x reference)
#include <cuda_runtime.h>

#define BB 32
#define NN 1024
#define KK 20
#define BN_ 32768          // BB*NN
#define NSLOT 64

// ---------------- scratch (static __device__, no allocations) ----------------
__device__ float g_cat[BN_ * 512];       // x1|x2|x3|x4 concatenated per point
__device__ float g_y[BN_ * 256];         // y = x @ Wa^T
__device__ float g_base[BN_ * 256];      // base = x @ (Wb-Wa)^T
__device__ float g_hmax[BN_ * 256];
__device__ float g_hmin[BN_ * 256];
__device__ int   g_idx[BN_ * KK];
__device__ float g_sumslot[NSLOT * 1024];
__device__ float g_sqslot[NSLOT * 1024];
__device__ float g_scale[1024];
__device__ float g_bias[1024];
__device__ unsigned g_bmaxk[BB * 1024];
__device__ unsigned g_bmink[BB * 1024];

__device__ __forceinline__ unsigned encf(float f) {
    int i = __float_as_int(f);
    return (i >= 0) ? ((unsigned)i | 0x80000000u) : ~((unsigned)i);
}
__device__ __forceinline__ float decf(unsigned u) {
    return __int_as_float((u & 0x80000000u) ? (int)(u ^ 0x80000000u) : (int)(~u));
}

// ---------------- init: zero slots, reset per-(b,o) max/min keys -------------
__global__ void k_init() {
    int i = blockIdx.x * blockDim.x + threadIdx.x;
    if (i < NSLOT * 1024) { g_sumslot[i] = 0.f; g_sqslot[i] = 0.f; }
    if (i < BB * 1024)    { g_bmaxk[i] = 0u;   g_bmink[i] = 0xFFFFFFFFu; }
}

// ---------------- stage1 y/base (C=3, O=64) ----------------------------------
__global__ void k_ybase1(const float* __restrict__ x, const float* __restrict__ W) {
    int bn = blockIdx.x;
    int o  = threadIdx.x;   // 64
    __shared__ float xs[3];
    if (o < 3) xs[o] = x[bn * 3 + o];
    __syncthreads();
    const float* w = W + o * 6;
    float y  = w[0] * xs[0] + w[1] * xs[1] + w[2] * xs[2];
    float bs = (w[3] - w[0]) * xs[0] + (w[4] - w[1]) * xs[1] + (w[5] - w[2]) * xs[2];
    g_y[bn * 64 + o]    = y;
    g_base[bn * 64 + o] = bs;
}

// ---------------- kNN: one thread per query, top-20 in registers -------------
template <int C>
__global__ void k_knn(const float* __restrict__ xin, int aoff, int lda) {
    constexpr int TS = 64;
    __shared__ float sc[TS][C];
    __shared__ float snorm[TS];
    const float* x = xin ? xin : (g_cat + aoff);

    int q = blockIdx.x * blockDim.x + threadIdx.x;  // global query, blockDim=128
    int b = q >> 10;
    int n = q & 1023;
    const float* xb = x + (size_t)b * NN * lda;

    float qv[C];
#pragma unroll
    for (int c = 0; c < C; c++) qv[c] = xb[(size_t)n * lda + c];
    float qq = 0.f;
#pragma unroll
    for (int c = 0; c < C; c++) qq += qv[c] * qv[c];

    float vals[KK]; int ids[KK];
#pragma unroll
    for (int i = 0; i < KK; i++) { vals[i] = -1e30f; ids[i] = 0; }

    for (int t = 0; t < NN / TS; t++) {
        __syncthreads();
        for (int i = threadIdx.x; i < TS * C; i += blockDim.x) {
            int r = i / C, c = i % C;
            sc[r][c] = xb[(size_t)(t * TS + r) * lda + c];
        }
        __syncthreads();
        if (threadIdx.x < TS) {
            float s = 0.f;
#pragma unroll
            for (int c = 0; c < C; c++) s += sc[threadIdx.x][c] * sc[threadIdx.x][c];
            snorm[threadIdx.x] = s;
        }
        __syncthreads();
        for (int mm = 0; mm < TS; mm++) {
            float acc = 0.f;
            if constexpr (C % 4 == 0) {
#pragma unroll
                for (int c4 = 0; c4 < C / 4; c4++) {
                    float4 v = *reinterpret_cast<const float4*>(&sc[mm][c4 * 4]);
                    acc += qv[c4 * 4 + 0] * v.x;
                    acc += qv[c4 * 4 + 1] * v.y;
                    acc += qv[c4 * 4 + 2] * v.z;
                    acc += qv[c4 * 4 + 3] * v.w;
                }
            } else {
#pragma unroll
                for (int c = 0; c < C; c++) acc += qv[c] * sc[mm][c];
            }
            float pd = 2.f * acc - qq - snorm[mm];
            if (pd > vals[KK - 1]) {
                int m = t * TS + mm;
#pragma unroll
                for (int i = KK - 1; i >= 0; i--) {
                    if (i > 0 && vals[i - 1] < pd) { vals[i] = vals[i - 1]; ids[i] = ids[i - 1]; }
                    else { vals[i] = pd; ids[i] = m; break; }
                }
            }
        }
    }
#pragma unroll
    for (int i = 0; i < KK; i++) g_idx[(size_t)q * KK + i] = ids[i];
}

// ---------------- gather-reduce over k neighbors -----------------------------
__global__ void k_edge_reduce(int O) {
    int bn = blockIdx.x;
    int o  = threadIdx.x;       // O threads
    int b  = bn >> 10;
    __shared__ int soff[KK];
    if (o < KK) soff[o] = ((b << 10) + g_idx[(size_t)bn * KK + o]) * O;
    __syncthreads();
    float bs = g_base[(size_t)bn * O + o];
    float mx = -1e30f, mn = 1e30f, s = 0.f, s2 = 0.f;
#pragma unroll
    for (int j = 0; j < KK; j++) {
        float v = g_y[soff[j] + o] + bs;
        mx = fmaxf(mx, v); mn = fminf(mn, v);
        s += v; s2 += v * v;
    }
    g_hmax[(size_t)bn * O + o] = mx;
    g_hmin[(size_t)bn * O + o] = mn;
    int slot = bn & (NSLOT - 1);
    atomicAdd(&g_sumslot[slot * 1024 + o], s);
    atomicAdd(&g_sqslot[slot * 1024 + o], s2);
}

// ---------------- BN stats finalize (and rezero slots) -----------------------
__global__ void k_stats(const float* __restrict__ g, const float* __restrict__ bt,
                        int O, float invcnt) {
    int o = blockIdx.x * blockDim.x + threadIdx.x;   // 1024 threads total
    float s = 0.f, s2 = 0.f;
    for (int sl = 0; sl < NSLOT; sl++) {
        s  += g_sumslot[sl * 1024 + o];
        s2 += g_sqslot[sl * 1024 + o];
        g_sumslot[sl * 1024 + o] = 0.f;
        g_sqslot[sl * 1024 + o]  = 0.f;
    }
    if (o < O) {
        float mean = s * invcnt;
        float var  = fmaxf(s2 * invcnt - mean * mean, 0.f);
        float sc   = g[o] * rsqrtf(var + 1e-5f);
        g_scale[o] = sc;
        g_bias[o]  = bt[o] - mean * sc;
    }
}

// ---------------- apply BN + LeakyReLU to max/min, write into cat ------------
__global__ void k_apply(int O, int coff) {
    int i = blockIdx.x * blockDim.x + threadIdx.x;
    if (i >= BN_ * O) return;
    int o  = i & (O - 1);        // O is a power of two
    int bn = i / O;
    float sc = g_scale[o];
    float v  = (sc >= 0.f) ? g_hmax[i] : g_hmin[i];
    float hv = fmaf(sc, v, g_bias[o]);
    g_cat[(size_t)bn * 512 + coff + o] = (hv >= 0.f) ? hv : 0.2f * hv;
}

// ---------------- tiled SGEMM: out(M x O) = cat_slice(M x K) @ W^T -----------
// STATS=false: write to g_y (outsel=0) or g_base (outsel=1)
// STATS=true : stage-5 epilogue (per-(b,o) max/min keys + channel sums)
template <bool STATS>
__global__ void k_gemm(int aoff, const float* __restrict__ Wa,
                       const float* __restrict__ Wsub, int ldw, int Ktot, int outsel) {
    __shared__ float As[16][64];
    __shared__ float Bs[16][64];
    const float* A = g_cat + aoff;
    const int lda = 512;
    const int m0 = blockIdx.x * 64;
    const int o0 = blockIdx.y * 64;
    const int tid = threadIdx.x;             // 128
    const int ty = tid >> 3, tx = tid & 7;   // 16 x 8
    const int lm = tid >> 1, lp = tid & 1;   // loader: row, half

    float acc[4][8];
#pragma unroll
    for (int i = 0; i < 4; i++)
#pragma unroll
        for (int j = 0; j < 8; j++) acc[i][j] = 0.f;

    for (int kt = 0; kt < Ktot; kt += 16) {
        const float* ap = A + (size_t)(m0 + lm) * lda + kt + lp * 8;
        float4 a0 = *reinterpret_cast<const float4*>(ap);
        float4 a1 = *reinterpret_cast<const float4*>(ap + 4);
        const float* wp = Wa + (size_t)(o0 + lm) * ldw + kt + lp * 8;
        float4 w0 = *reinterpret_cast<const float4*>(wp);
        float4 w1 = *reinterpret_cast<const float4*>(wp + 4);
        if (Wsub) {
            const float* sp = Wsub + (size_t)(o0 + lm) * ldw + kt + lp * 8;
            float4 s0 = *reinterpret_cast<const float4*>(sp);
            float4 s1 = *reinterpret_cast<const float4*>(sp + 4);
            w0.x -= s0.x; w0.y -= s0.y; w0.z -= s0.z; w0.w -= s0.w;
            w1.x -= s1.x; w1.y -= s1.y; w1.z -= s1.z; w1.w -= s1.w;
        }
        __syncthreads();
        As[lp * 8 + 0][lm] = a0.x; As[lp * 8 + 1][lm] = a0.y;
        As[lp * 8 + 2][lm] = a0.z; As[lp * 8 + 3][lm] = a0.w;
        As[lp * 8 + 4][lm] = a1.x; As[lp * 8 + 5][lm] = a1.y;
        As[lp * 8 + 6][lm] = a1.z; As[lp * 8 + 7][lm] = a1.w;
        Bs[lp * 8 + 0][lm] = w0.x; Bs[lp * 8 + 1][lm] = w0.y;
        Bs[lp * 8 + 2][lm] = w0.z; Bs[lp * 8 + 3][lm] = w0.w;
        Bs[lp * 8 + 4][lm] = w1.x; Bs[lp * 8 + 5][lm] = w1.y;
        Bs[lp * 8 + 6][lm] = w1.z; Bs[lp * 8 + 7][lm] = w1.w;
        __syncthreads();
#pragma unroll
        for (int kk = 0; kk < 16; kk++) {
            float4 av = *reinterpret_cast<const float4*>(&As[kk][ty * 4]);
            float4 b0 = *reinterpret_cast<const float4*>(&Bs[kk][tx * 8]);
            float4 b1 = *reinterpret_cast<const float4*>(&Bs[kk][tx * 8 + 4]);
            float aa[4] = {av.x, av.y, av.z, av.w};
            float bb[8] = {b0.x, b0.y, b0.z, b0.w, b1.x, b1.y, b1.z, b1.w};
#pragma unroll
            for (int i = 0; i < 4; i++)
#pragma unroll
                for (int j = 0; j < 8; j++) acc[i][j] = fmaf(aa[i], bb[j], acc[i][j]);
        }
    }

    if (!STATS) {
        float* Cout = outsel ? g_base : g_y;
        const int ldc = gridDim.y * 64;
#pragma unroll
        for (int i = 0; i < 4; i++)
#pragma unroll
            for (int j = 0; j < 8; j++)
                Cout[(size_t)(m0 + ty * 4 + i) * ldc + o0 + tx * 8 + j] = acc[i][j];
    } else {
        int b = m0 >> 10;
        int slot = blockIdx.x & (NSLOT - 1);
#pragma unroll
        for (int j = 0; j < 8; j++) {
            int o = o0 + tx * 8 + j;
            float mx = acc[0][j], mn = acc[0][j], s = acc[0][j], s2 = acc[0][j] * acc[0][j];
#pragma unroll
            for (int i = 1; i < 4; i++) {
                float v = acc[i][j];
                mx = fmaxf(mx, v); mn = fminf(mn, v);
                s += v; s2 += v * v;
            }
            atomicMax(&g_bmaxk[b * 1024 + o], encf(mx));
            atomicMin(&g_bmink[b * 1024 + o], encf(mn));
            atomicAdd(&g_sumslot[slot * 1024 + o], s);
            atomicAdd(&g_sqslot[slot * 1024 + o], s2);
        }
    }
}

// ---------------- stage5 finalize: BN + LReLU on per-(b,o) extremum ----------
__global__ void k_final5(float* __restrict__ out) {
    int i = blockIdx.x * blockDim.x + threadIdx.x;   // 32768
    int o = i & 1023;
    float sc = g_scale[o];
    float v  = decf((sc >= 0.f) ? g_bmaxk[i] : g_bmink[i]);
    float hv = fmaf(sc, v, g_bias[o]);
    out[i] = (hv >= 0.f) ? hv : 0.2f * hv;
}

// ---------------- orchestration ----------------------------------------------
extern "C" void kernel_launch(void* const* d_in, const int* in_sizes, int n_in,
                              void* d_out, int out_size) {
    const float* x = (const float*)d_in[0];
    const float *W1 = (const float*)d_in[1],  *G1 = (const float*)d_in[2],  *B1 = (const float*)d_in[3];
    const float *W2 = (const float*)d_in[4],  *G2 = (const float*)d_in[5],  *B2 = (const float*)d_in[6];
    const float *W3 = (const float*)d_in[7],  *G3 = (const float*)d_in[8],  *B3 = (const float*)d_in[9];
    const float *W4 = (const float*)d_in[10], *G4 = (const float*)d_in[11], *B4 = (const float*)d_in[12];
    const float *W5 = (const float*)d_in[13], *G5 = (const float*)d_in[14], *B5 = (const float*)d_in[15];
    float* out = (float*)d_out;

    const float invE = 1.f / (float)((size_t)BN_ * KK);

    k_init<<<256, 256>>>();

    // ---- Stage 1: C=3, O=64, write cat[0:64) ----
    k_ybase1<<<BN_, 64>>>(x, W1);
    k_knn<3><<<BN_ / 128, 128>>>(x, 0, 3);
    k_edge_reduce<<<BN_, 64>>>(64);
    k_stats<<<4, 256>>>(G1, B1, 64, invE);
    k_apply<<<BN_ * 64 / 256, 256>>>(64, 0);

    // ---- Stage 2: in=cat[0:64), C=64, O=64, write cat[64:128) ----
    k_gemm<false><<<dim3(512, 1), 128>>>(0, W2,      nullptr, 128, 64, 0);
    k_gemm<false><<<dim3(512, 1), 128>>>(0, W2 + 64, W2,      128, 64, 1);
    k_knn<64><<<BN_ / 128, 128>>>(nullptr, 0, 512);
    k_edge_reduce<<<BN_, 64>>>(64);
    k_stats<<<4, 256>>>(G2, B2, 64, invE);
    k_apply<<<BN_ * 64 / 256, 256>>>(64, 64);

    // ---- Stage 3: in=cat[64:128), C=64, O=128, write cat[128:256) ----
    k_gemm<false><<<dim3(512, 2), 128>>>(64, W3,      nullptr, 128, 64, 0);
    k_gemm<false><<<dim3(512, 2), 128>>>(64, W3 + 64, W3,      128, 64, 1);
    k_knn<64><<<BN_ / 128, 128>>>(nullptr, 64, 512);
    k_edge_reduce<<<BN_, 128>>>(128);
    k_stats<<<4, 256>>>(G3, B3, 128, invE);
    k_apply<<<BN_ * 128 / 256, 256>>>(128, 128);

    // ---- Stage 4: in=cat[128:256), C=128, O=256, write cat[256:512) ----
    k_gemm<false><<<dim3(512, 4), 128>>>(128, W4,       nullptr, 256, 128, 0);
    k_gemm<false><<<dim3(512, 4), 128>>>(128, W4 + 128, W4,      256, 128, 1);
    k_knn<128><<<BN_ / 128, 128>>>(nullptr, 128, 512);
    k_edge_reduce<<<BN_, 256>>>(256);
    k_stats<<<4, 256>>>(G4, B4, 256, invE);
    k_apply<<<BN_ * 256 / 256, 256>>>(256, 256);

    // ---- Stage 5: FC 512->1024 + BN + LReLU + max over points ----
    k_gemm<true><<<dim3(512, 16), 128>>>(0, W5, nullptr, 512, 512, 0);
    k_stats<<<4, 256>>>(G5, B5, 1024, 1.f / (float)BN_);
    k_final5<<<128, 256>>>(out);
}

// round 2
// speedup vs baseline: 2.6278x; 2.6278x over previous
#include <cuda_runtime.h>

#define BB 32
#define NN 1024
#define KK 20
#define BN_ 32768          // BB*NN
#define NSLOT 64

// ---------------- scratch (static __device__, no allocations) ----------------
__device__ float g_cat[BN_ * 512];       // x1|x2|x3|x4 concatenated per point
__device__ float g_y[BN_ * 256];         // y = x @ Wa^T
__device__ float g_base[BN_ * 256];      // base = x @ (Wb-Wa)^T
__device__ float g_hmax[BN_ * 256];
__device__ float g_hmin[BN_ * 256];
__device__ float g_pd[(size_t)BB * NN * NN];   // per-batch gram matrix (134MB)
__device__ float g_norm[BN_];
__device__ int   g_idx[BN_ * KK];
__device__ float g_sumslot[NSLOT * 1024];
__device__ float g_sqslot[NSLOT * 1024];
__device__ float g_scale[1024];
__device__ float g_bias[1024];
__device__ unsigned g_bmaxk[BB * 1024];
__device__ unsigned g_bmink[BB * 1024];

__device__ __forceinline__ unsigned encf(float f) {
    int i = __float_as_int(f);
    return (i >= 0) ? ((unsigned)i | 0x80000000u) : ~((unsigned)i);
}
__device__ __forceinline__ float decf(unsigned u) {
    return __int_as_float((u & 0x80000000u) ? (int)(u ^ 0x80000000u) : (int)(~u));
}

// ---------------- init ------------------------------------------------------
__global__ void k_init() {
    int i = blockIdx.x * blockDim.x + threadIdx.x;
    if (i < NSLOT * 1024) { g_sumslot[i] = 0.f; g_sqslot[i] = 0.f; }
    if (i < BB * 1024)    { g_bmaxk[i] = 0u;   g_bmink[i] = 0xFFFFFFFFu; }
}

// ---------------- stage1 y/base (C=3, O=64) ---------------------------------
__global__ void k_ybase1(const float* __restrict__ x, const float* __restrict__ W) {
    int bn = blockIdx.x;
    int o  = threadIdx.x;   // 64
    __shared__ float xs[3];
    if (o < 3) xs[o] = x[bn * 3 + o];
    __syncthreads();
    const float* w = W + o * 6;
    float y  = w[0] * xs[0] + w[1] * xs[1] + w[2] * xs[2];
    float bs = (w[3] - w[0]) * xs[0] + (w[4] - w[1]) * xs[1] + (w[5] - w[2]) * xs[2];
    g_y[bn * 64 + o]    = y;
    g_base[bn * 64 + o] = bs;
}

// ---------------- kNN for C=3 only (low register use) -----------------------
__global__ void k_knn3(const float* __restrict__ x) {
    constexpr int TS = 64;
    __shared__ float sc[TS][3];
    __shared__ float snorm[TS];
    int q = blockIdx.x * blockDim.x + threadIdx.x;  // blockDim=128
    int b = q >> 10;
    const float* xb = x + (size_t)b * NN * 3;
    int n = q & 1023;
    float q0 = xb[n * 3 + 0], q1 = xb[n * 3 + 1], q2 = xb[n * 3 + 2];
    float qq = q0 * q0 + q1 * q1 + q2 * q2;

    float vals[KK]; int ids[KK];
#pragma unroll
    for (int i = 0; i < KK; i++) { vals[i] = -1e30f; ids[i] = 0; }

    for (int t = 0; t < NN / TS; t++) {
        __syncthreads();
        for (int i = threadIdx.x; i < TS * 3; i += blockDim.x) {
            sc[i / 3][i % 3] = xb[(size_t)t * TS * 3 + i];
        }
        __syncthreads();
        if (threadIdx.x < TS) {
            float a = sc[threadIdx.x][0], bq = sc[threadIdx.x][1], c = sc[threadIdx.x][2];
            snorm[threadIdx.x] = a * a + bq * bq + c * c;
        }
        __syncthreads();
        for (int mm = 0; mm < TS; mm++) {
            float acc = q0 * sc[mm][0] + q1 * sc[mm][1] + q2 * sc[mm][2];
            float pd = (2.f * acc - qq) - snorm[mm];
            if (pd > vals[KK - 1]) {
                float cv = pd; int ci = t * TS + mm;
#pragma unroll
                for (int i = 0; i < KK; i++) {
                    bool sw = cv > vals[i];
                    float tv = vals[i]; int ti = ids[i];
                    vals[i] = sw ? cv : tv; ids[i] = sw ? ci : ti;
                    cv = sw ? tv : cv;  ci = sw ? ti : ci;
                }
            }
        }
    }
#pragma unroll
    for (int i = 0; i < KK; i++) g_idx[(size_t)q * KK + i] = ids[i];
}

// ---------------- diag of gram -> candidate norms ---------------------------
__global__ void k_diag() {
    int q = blockIdx.x * blockDim.x + threadIdx.x;
    if (q < BN_) g_norm[q] = g_pd[(size_t)q * NN + (q & 1023)];
}

// ---------------- top-20 select from gram rows ------------------------------
__global__ __launch_bounds__(64) void k_select() {
    __shared__ float sm[64][65];
    __shared__ float snrm[64];
    int t = threadIdx.x;           // 64 threads, 1 query each
    int q0 = blockIdx.x * 64;
    int b  = q0 >> 10;
    float qq = g_norm[q0 + t];

    float vals[KK]; int ids[KK];
#pragma unroll
    for (int i = 0; i < KK; i++) { vals[i] = -1e30f; ids[i] = 0; }

    for (int tile = 0; tile < 16; tile++) {
        int c0 = tile * 64;
        __syncthreads();
#pragma unroll
        for (int it = 0; it < 16; it++) {
            int idx4 = it * 64 + t;
            int r = idx4 >> 4, c4 = (idx4 & 15) * 4;
            float4 v = *reinterpret_cast<const float4*>(&g_pd[(size_t)(q0 + r) * NN + c0 + c4]);
            sm[r][c4] = v.x; sm[r][c4 + 1] = v.y; sm[r][c4 + 2] = v.z; sm[r][c4 + 3] = v.w;
        }
        snrm[t] = g_norm[(b << 10) + c0 + t];
        __syncthreads();
        for (int j = 0; j < 64; j++) {
            float key = (2.f * sm[t][j] - qq) - snrm[j];
            if (key > vals[KK - 1]) {
                float cv = key; int ci = c0 + j;
#pragma unroll
                for (int i = 0; i < KK; i++) {
                    bool sw = cv > vals[i];
                    float tv = vals[i]; int ti = ids[i];
                    vals[i] = sw ? cv : tv; ids[i] = sw ? ci : ti;
                    cv = sw ? tv : cv;  ci = sw ? ti : ci;
                }
            }
        }
    }
#pragma unroll
    for (int i = 0; i < KK; i++) g_idx[(size_t)(q0 + t) * KK + i] = ids[i];
}

// ---------------- gather-reduce over k neighbors ----------------------------
__global__ void k_edge_reduce(int O) {
    int bn = blockIdx.x;
    int o  = threadIdx.x;       // O threads
    int b  = bn >> 10;
    __shared__ int soff[KK];
    if (o < KK) soff[o] = ((b << 10) + g_idx[(size_t)bn * KK + o]) * O;
    __syncthreads();
    float bs = g_base[(size_t)bn * O + o];
    float mx = -1e30f, mn = 1e30f, s = 0.f, s2 = 0.f;
#pragma unroll
    for (int j = 0; j < KK; j++) {
        float v = g_y[soff[j] + o] + bs;
        mx = fmaxf(mx, v); mn = fminf(mn, v);
        s += v; s2 += v * v;
    }
    g_hmax[(size_t)bn * O + o] = mx;
    g_hmin[(size_t)bn * O + o] = mn;
    int slot = bn & (NSLOT - 1);
    atomicAdd(&g_sumslot[slot * 1024 + o], s);
    atomicAdd(&g_sqslot[slot * 1024 + o], s2);
}

// ---------------- BN stats finalize (and rezero slots) ----------------------
__global__ void k_stats(const float* __restrict__ g, const float* __restrict__ bt,
                        int O, float invcnt) {
    int o = blockIdx.x * blockDim.x + threadIdx.x;   // 1024 threads total
    float s = 0.f, s2 = 0.f;
    for (int sl = 0; sl < NSLOT; sl++) {
        s  += g_sumslot[sl * 1024 + o];
        s2 += g_sqslot[sl * 1024 + o];
        g_sumslot[sl * 1024 + o] = 0.f;
        g_sqslot[sl * 1024 + o]  = 0.f;
    }
    if (o < O) {
        float mean = s * invcnt;
        float var  = fmaxf(s2 * invcnt - mean * mean, 0.f);
        float sc   = g[o] * rsqrtf(var + 1e-5f);
        g_scale[o] = sc;
        g_bias[o]  = bt[o] - mean * sc;
    }
}

// ---------------- apply BN + LeakyReLU to max/min, write into cat -----------
__global__ void k_apply(int O, int coff) {
    int i = blockIdx.x * blockDim.x + threadIdx.x;
    if (i >= BN_ * O) return;
    int o  = i & (O - 1);        // O is a power of two
    int bn = i / O;
    float sc = g_scale[o];
    float v  = (sc >= 0.f) ? g_hmax[i] : g_hmin[i];
    float hv = fmaf(sc, v, g_bias[o]);
    g_cat[(size_t)bn * 512 + coff + o] = (hv >= 0.f) ? hv : 0.2f * hv;
}

// ---------------- big tiled SGEMM: 128 x BNT tile, 256 threads --------------
// A = g_cat+aoff (lda 512). B = W rows (ldw) or, if GRAM, same-batch A rows.
// SUB: B -= Wsub. STATS: stage-5 epilogue. Else write g_y/g_base/g_pd.
template <int BNT, int TN, bool SUB, bool STATS, bool GRAM>
__global__ __launch_bounds__(256) void k_gemm2(
        int aoff, const float* __restrict__ Wa, const float* __restrict__ Wsub,
        int ldw, int Ktot, int ldc, int outsel) {
    __shared__ float As[16][128];
    __shared__ float Bs[16][BNT];
    const float* A = g_cat + aoff;
    const int lda = 512;
    const int m0 = blockIdx.x * 128;
    const int o0 = blockIdx.y * BNT;
    const int tid = threadIdx.x;
    const int trow = tid >> 4;   // 0..15
    const int tcol = tid & 15;   // 0..15

    float acc[8][TN];
#pragma unroll
    for (int i = 0; i < 8; i++)
#pragma unroll
        for (int j = 0; j < TN; j++) acc[i][j] = 0.f;

    const int arow = tid >> 1, akoff = (tid & 1) * 8;
    int brow, bkoff;
    if (BNT == 128) { brow = tid >> 1; bkoff = (tid & 1) * 8; }
    else            { brow = tid >> 2; bkoff = (tid & 3) * 4; }

    const float* bbaseptr;
    int ldb;
    if (GRAM) { bbaseptr = A + (size_t)((m0 & ~1023) + o0) * lda; ldb = lda; }
    else      { bbaseptr = Wa + (size_t)o0 * ldw;                  ldb = ldw; }

    for (int kt = 0; kt < Ktot; kt += 16) {
        const float* ap = A + (size_t)(m0 + arow) * lda + kt + akoff;
        float4 a0 = *reinterpret_cast<const float4*>(ap);
        float4 a1 = *reinterpret_cast<const float4*>(ap + 4);
        const float* bp = bbaseptr + (size_t)brow * ldb + kt + bkoff;
        float4 b0 = *reinterpret_cast<const float4*>(bp);
        float4 b1;
        if constexpr (BNT == 128) b1 = *reinterpret_cast<const float4*>(bp + 4);
        if constexpr (SUB) {
            const float* sp = Wsub + (size_t)(o0 + brow) * ldw + kt + bkoff;
            float4 s0 = *reinterpret_cast<const float4*>(sp);
            b0.x -= s0.x; b0.y -= s0.y; b0.z -= s0.z; b0.w -= s0.w;
            if constexpr (BNT == 128) {
                float4 s1 = *reinterpret_cast<const float4*>(sp + 4);
                b1.x -= s1.x; b1.y -= s1.y; b1.z -= s1.z; b1.w -= s1.w;
            }
        }
        __syncthreads();
        As[akoff + 0][arow] = a0.x; As[akoff + 1][arow] = a0.y;
        As[akoff + 2][arow] = a0.z; As[akoff + 3][arow] = a0.w;
        As[akoff + 4][arow] = a1.x; As[akoff + 5][arow] = a1.y;
        As[akoff + 6][arow] = a1.z; As[akoff + 7][arow] = a1.w;
        Bs[bkoff + 0][brow] = b0.x; Bs[bkoff + 1][brow] = b0.y;
        Bs[bkoff + 2][brow] = b0.z; Bs[bkoff + 3][brow] = b0.w;
        if constexpr (BNT == 128) {
            Bs[bkoff + 4][brow] = b1.x; Bs[bkoff + 5][brow] = b1.y;
            Bs[bkoff + 6][brow] = b1.z; Bs[bkoff + 7][brow] = b1.w;
        }
        __syncthreads();
#pragma unroll
        for (int kk = 0; kk < 16; kk++) {
            float av[8];
            *reinterpret_cast<float4*>(&av[0]) = *reinterpret_cast<const float4*>(&As[kk][trow * 8]);
            *reinterpret_cast<float4*>(&av[4]) = *reinterpret_cast<const float4*>(&As[kk][trow * 8 + 4]);
            float bv[TN];
            *reinterpret_cast<float4*>(&bv[0]) = *reinterpret_cast<const float4*>(&Bs[kk][tcol * TN]);
            if constexpr (TN == 8)
                *reinterpret_cast<float4*>(&bv[4]) = *reinterpret_cast<const float4*>(&Bs[kk][tcol * TN + 4]);
#pragma unroll
            for (int i = 0; i < 8; i++)
#pragma unroll
                for (int j = 0; j < TN; j++) acc[i][j] = fmaf(av[i], bv[j], acc[i][j]);
        }
    }

    if constexpr (STATS) {
        // stage-5: per-thread reduce 8 rows, then block reduce in As scratch
        int b = m0 >> 10;
        int slot = blockIdx.x & (NSLOT - 1);
        float mx[8], mn[8], sv[8], s2v[8];
#pragma unroll
        for (int j = 0; j < 8; j++) {
            float v = acc[0][j];
            mx[j] = v; mn[j] = v; sv[j] = v; s2v[j] = v * v;
#pragma unroll
            for (int i = 1; i < 8; i++) {
                float w = acc[i][j];
                mx[j] = fmaxf(mx[j], w); mn[j] = fminf(mn[j], w);
                sv[j] += w; s2v[j] += w * w;
            }
        }
        __syncthreads();
#pragma unroll
        for (int j = 0; j < 8; j++) As[trow][tcol * 8 + j] = mx[j];
        __syncthreads();
        if (tid < 128) {
            float r = As[0][tid];
#pragma unroll
            for (int t = 1; t < 16; t++) r = fmaxf(r, As[t][tid]);
            atomicMax(&g_bmaxk[b * 1024 + o0 + tid], encf(r));
        }
        __syncthreads();
#pragma unroll
        for (int j = 0; j < 8; j++) As[trow][tcol * 8 + j] = mn[j];
        __syncthreads();
        if (tid < 128) {
            float r = As[0][tid];
#pragma unroll
            for (int t = 1; t < 16; t++) r = fminf(r, As[t][tid]);
            atomicMin(&g_bmink[b * 1024 + o0 + tid], encf(r));
        }
        __syncthreads();
#pragma unroll
        for (int j = 0; j < 8; j++) As[trow][tcol * 8 + j] = sv[j];
        __syncthreads();
        if (tid < 128) {
            float r = 0.f;
#pragma unroll
            for (int t = 0; t < 16; t++) r += As[t][tid];
            atomicAdd(&g_sumslot[slot * 1024 + o0 + tid], r);
        }
        __syncthreads();
#pragma unroll
        for (int j = 0; j < 8; j++) As[trow][tcol * 8 + j] = s2v[j];
        __syncthreads();
        if (tid < 128) {
            float r = 0.f;
#pragma unroll
            for (int t = 0; t < 16; t++) r += As[t][tid];
            atomicAdd(&g_sqslot[slot * 1024 + o0 + tid], r);
        }
    } else {
        float* cout = GRAM ? g_pd : (outsel ? g_base : g_y);
#pragma unroll
        for (int i = 0; i < 8; i++) {
            int row = m0 + trow * 8 + i;
            float* cp = cout + (size_t)row * ldc + o0 + tcol * TN;
            float4 v0 = make_float4(acc[i][0], acc[i][1], acc[i][2], acc[i][3]);
            *reinterpret_cast<float4*>(cp) = v0;
            if constexpr (TN == 8) {
                float4 v1 = make_float4(acc[i][4], acc[i][5], acc[i][6], acc[i][7]);
                *reinterpret_cast<float4*>(cp + 4) = v1;
            }
        }
    }
}

// ---------------- stage5 finalize: BN + LReLU on per-(b,o) extremum ---------
__global__ void k_final5(float* __restrict__ out) {
    int i = blockIdx.x * blockDim.x + threadIdx.x;   // 32768
    int o = i & 1023;
    float sc = g_scale[o];
    float v  = decf((sc >= 0.f) ? g_bmaxk[i] : g_bmink[i]);
    float hv = fmaf(sc, v, g_bias[o]);
    out[i] = (hv >= 0.f) ? hv : 0.2f * hv;
}

// ---------------- orchestration ---------------------------------------------
extern "C" void kernel_launch(void* const* d_in, const int* in_sizes, int n_in,
                              void* d_out, int out_size) {
    const float* x = (const float*)d_in[0];
    const float *W1 = (const float*)d_in[1],  *G1 = (const float*)d_in[2],  *B1 = (const float*)d_in[3];
    const float *W2 = (const float*)d_in[4],  *G2 = (const float*)d_in[5],  *B2 = (const float*)d_in[6];
    const float *W3 = (const float*)d_in[7],  *G3 = (const float*)d_in[8],  *B3 = (const float*)d_in[9];
    const float *W4 = (const float*)d_in[10], *G4 = (const float*)d_in[11], *B4 = (const float*)d_in[12];
    const float *W5 = (const float*)d_in[13], *G5 = (const float*)d_in[14], *B5 = (const float*)d_in[15];
    float* out = (float*)d_out;

    const float invE = 1.f / (float)((size_t)BN_ * KK);

    k_init<<<256, 256>>>();

    // ---- Stage 1: C=3, O=64, write cat[0:64) ----
    k_ybase1<<<BN_, 64>>>(x, W1);
    k_knn3<<<BN_ / 128, 128>>>(x);
    k_edge_reduce<<<BN_, 64>>>(64);
    k_stats<<<4, 256>>>(G1, B1, 64, invE);
    k_apply<<<BN_ * 64 / 256, 256>>>(64, 0);

    // ---- Stage 2: in=cat[0:64), C=64, O=64 -> cat[64:128) ----
    k_gemm2<64, 4, false, false, false><<<dim3(256, 1), 256>>>(0, W2,      nullptr, 128, 64, 64, 0);
    k_gemm2<64, 4, true,  false, false><<<dim3(256, 1), 256>>>(0, W2 + 64, W2,      128, 64, 64, 1);
    k_gemm2<128, 8, false, false, true><<<dim3(256, 8), 256>>>(0, nullptr, nullptr, 0, 64, 1024, 0);
    k_diag<<<BN_ / 256, 256>>>();
    k_select<<<BN_ / 64, 64>>>();
    k_edge_reduce<<<BN_, 64>>>(64);
    k_stats<<<4, 256>>>(G2, B2, 64, invE);
    k_apply<<<BN_ * 64 / 256, 256>>>(64, 64);

    // ---- Stage 3: in=cat[64:128), C=64, O=128 -> cat[128:256) ----
    k_gemm2<128, 8, false, false, false><<<dim3(256, 1), 256>>>(64, W3,      nullptr, 128, 64, 128, 0);
    k_gemm2<128, 8, true,  false, false><<<dim3(256, 1), 256>>>(64, W3 + 64, W3,      128, 64, 128, 1);
    k_gemm2<128, 8, false, false, true><<<dim3(256, 8), 256>>>(64, nullptr, nullptr, 0, 64, 1024, 0);
    k_diag<<<BN_ / 256, 256>>>();
    k_select<<<BN_ / 64, 64>>>();
    k_edge_reduce<<<BN_, 128>>>(128);
    k_stats<<<4, 256>>>(G3, B3, 128, invE);
    k_apply<<<BN_ * 128 / 256, 256>>>(128, 128);

    // ---- Stage 4: in=cat[128:256), C=128, O=256 -> cat[256:512) ----
    k_gemm2<128, 8, false, false, false><<<dim3(256, 2), 256>>>(128, W4,       nullptr, 256, 128, 256, 0);
    k_gemm2<128, 8, true,  false, false><<<dim3(256, 2), 256>>>(128, W4 + 128, W4,      256, 128, 256, 1);
    k_gemm2<128, 8, false, false, true><<<dim3(256, 8), 256>>>(128, nullptr, nullptr, 0, 128, 1024, 0);
    k_diag<<<BN_ / 256, 256>>>();
    k_select<<<BN_ / 64, 64>>>();
    k_edge_reduce<<<BN_, 256>>>(256);
    k_stats<<<4, 256>>>(G4, B4, 256, invE);
    k_apply<<<BN_ * 256 / 256, 256>>>(256, 256);

    // ---- Stage 5: FC 512->1024 + BN + LReLU + max over points ----
    k_gemm2<128, 8, false, true, false><<<dim3(256, 8), 256>>>(0, W5, nullptr, 512, 512, 1024, 0);
    k_stats<<<4, 256>>>(G5, B5, 1024, 1.f / (float)BN_);
    k_final5<<<128, 256>>>(out);
}